// round 10
// baseline (speedup 1.0000x reference)
#include <cuda_runtime.h>
#include <cstdint>
#include <cstddef>

#define D_MODEL 1024
#define NHEAD   16
#define DK      64
#define BATCH   4
#define SEQ     1024
#define M_TOK   (BATCH*SEQ)    // 4096

#define QB   32     // q rows per attention block
#define CK   128    // k/v chunk columns
#define KPAD 76     // padded K-chunk row length (floats) -> conflict-free LDS.128

// scratch: qh, kh, vh, o_concat, x  (5 x 16MB)
#define NPH (BATCH*NHEAD*SEQ*DK)   // 4194304
__device__ float g_scratch[(size_t)5 * NPH];

// ---------------------------------------------------------------------------
// SGEMM (NT): C[M,N] = A[M,K] * W[N,K]^T + bias  (M=4096, N=K=1024)
// MODE 0: scatter to head layout dst[((b*16+h)*1024+s)*64+d]
// MODE 1: dst[m*1024+n] = C + bias + residual
// ---------------------------------------------------------------------------
template<int MODE>
__global__ __launch_bounds__(256) void sgemm_nt(
    const float* __restrict__ A, const float* __restrict__ W,
    const float* __restrict__ bias, const float* __restrict__ res,
    float* __restrict__ dst)
{
    const int K = D_MODEL;
    __shared__ float As[8][128];
    __shared__ float Bs[8][128];
    const int tid = threadIdx.x;
    const int m0 = blockIdx.y * 128;
    const int n0 = blockIdx.x * 128;
    const int lr = tid >> 1;           // 0..127
    const int lc = (tid & 1) << 2;     // 0 or 4
    const int ty = tid >> 4;           // 0..15
    const int tx = tid & 15;           // 0..15

    float acc[8][8];
#pragma unroll
    for (int i = 0; i < 8; i++)
#pragma unroll
        for (int j = 0; j < 8; j++) acc[i][j] = 0.f;

    const float* Ap = A + (size_t)(m0 + lr) * K + lc;
    const float* Wp = W + (size_t)(n0 + lr) * K + lc;

    for (int kt = 0; kt < K; kt += 8) {
        float4 a4 = *(const float4*)(Ap + kt);
        float4 b4 = *(const float4*)(Wp + kt);
        __syncthreads();
        As[lc+0][lr] = a4.x; As[lc+1][lr] = a4.y; As[lc+2][lr] = a4.z; As[lc+3][lr] = a4.w;
        Bs[lc+0][lr] = b4.x; Bs[lc+1][lr] = b4.y; Bs[lc+2][lr] = b4.z; Bs[lc+3][lr] = b4.w;
        __syncthreads();
#pragma unroll
        for (int kk = 0; kk < 8; kk++) {
            float4 a0 = *(const float4*)&As[kk][ty*4];
            float4 a1 = *(const float4*)&As[kk][64 + ty*4];
            float4 b0 = *(const float4*)&Bs[kk][tx*4];
            float4 b1 = *(const float4*)&Bs[kk][64 + tx*4];
            float ar[8] = {a0.x,a0.y,a0.z,a0.w,a1.x,a1.y,a1.z,a1.w};
            float br[8] = {b0.x,b0.y,b0.z,b0.w,b1.x,b1.y,b1.z,b1.w};
#pragma unroll
            for (int i = 0; i < 8; i++)
#pragma unroll
                for (int j = 0; j < 8; j++)
                    acc[i][j] = fmaf(ar[i], br[j], acc[i][j]);
        }
    }

#pragma unroll
    for (int i = 0; i < 8; i++) {
        int m = m0 + ((i < 4) ? (ty*4 + i) : (64 + ty*4 + i - 4));
#pragma unroll
        for (int j = 0; j < 8; j++) {
            int n = n0 + ((j < 4) ? (tx*4 + j) : (64 + tx*4 + j - 4));
            float v = acc[i][j] + bias[n];
            if (MODE == 0) {
                int bb = m >> 10, ss = m & 1023, hh = n >> 6, dd = n & 63;
                dst[(((size_t)(bb*NHEAD + hh) * SEQ + ss) << 6) + dd] = v;
            } else {
                size_t idx = (size_t)m * D_MODEL + n;
                dst[idx] = v + res[idx];
            }
        }
    }
}

// ---------------------------------------------------------------------------
// Fused attention: per (b,h, 32-row q block):
//   scores(32x1024) in smem -> softmax -> write attn to gmem -> O = P @ V
// No 1/sqrt(dk) scaling (faithful to reference).
// ---------------------------------------------------------------------------
__global__ __launch_bounds__(256) void attn_kernel(
    const float* __restrict__ qh, const float* __restrict__ kh,
    const float* __restrict__ vh,
    float* __restrict__ attn_out, float* __restrict__ o_out)
{
    extern __shared__ float sm[];
    float* P  = sm;                  // [32][1024]
    float* Qs = P + QB*SEQ;          // [32][64]
    float* KV = Qs + QB*DK;          // [128][76] for K (padded) / [128][64] for V

    const int tid  = threadIdx.x;
    const int bh   = blockIdx.y;         // b*16 + h
    const int qb   = blockIdx.x;         // 0..31
    const int b    = bh >> 4, h = bh & 15;
    const int warp = tid >> 5, lane = tid & 31;
    const int r0   = warp * 4;           // this warp's 4 rows

    // load Q tile (contiguous copy)
    const float* qbase = qh + (size_t)bh * SEQ * DK + (size_t)qb * QB * DK;
#pragma unroll
    for (int f = tid; f < QB*DK/4; f += 256)
        ((float4*)Qs)[f] = ((const float4*)qbase)[f];

    float accO[4][2] = {{0.f,0.f},{0.f,0.f},{0.f,0.f},{0.f,0.f}};

    // ---- scores: S[i][j] = Q[i] . K[j] ----
    for (int kc = 0; kc < SEQ/CK; kc++) {
        __syncthreads();
        const float* kbase = kh + (size_t)bh * SEQ * DK + (size_t)kc * CK * DK;
        for (int f = tid; f < CK*DK/4; f += 256) {
            int j = f >> 4, k4 = f & 15;
            float4 kv4 = ((const float4*)kbase)[f];
            *(float4*)&KV[j*KPAD + k4*4] = kv4;
        }
        __syncthreads();

        float acc[4][4];
#pragma unroll
        for (int ii = 0; ii < 4; ii++)
#pragma unroll
            for (int jj = 0; jj < 4; jj++) acc[ii][jj] = 0.f;

#pragma unroll 4
        for (int k4 = 0; k4 < DK/4; k4++) {
            float4 q0 = *(const float4*)&Qs[(r0+0)*DK + k4*4];
            float4 q1 = *(const float4*)&Qs[(r0+1)*DK + k4*4];
            float4 q2 = *(const float4*)&Qs[(r0+2)*DK + k4*4];
            float4 q3 = *(const float4*)&Qs[(r0+3)*DK + k4*4];
#pragma unroll
            for (int jj = 0; jj < 4; jj++) {
                float4 kv4 = *(const float4*)&KV[(lane + 32*jj)*KPAD + k4*4];
                acc[0][jj] += q0.x*kv4.x + q0.y*kv4.y + q0.z*kv4.z + q0.w*kv4.w;
                acc[1][jj] += q1.x*kv4.x + q1.y*kv4.y + q1.z*kv4.z + q1.w*kv4.w;
                acc[2][jj] += q2.x*kv4.x + q2.y*kv4.y + q2.z*kv4.z + q2.w*kv4.w;
                acc[3][jj] += q3.x*kv4.x + q3.y*kv4.y + q3.z*kv4.z + q3.w*kv4.w;
            }
        }
#pragma unroll
        for (int ii = 0; ii < 4; ii++)
#pragma unroll
            for (int jj = 0; jj < 4; jj++)
                P[(r0+ii)*SEQ + kc*CK + lane + 32*jj] = acc[ii][jj];
    }

    // ---- softmax on this warp's own 4 rows + write attn to gmem ----
    float* attn_base = attn_out + ((size_t)(h*BATCH + b) * SEQ + (size_t)qb*QB) * SEQ;
#pragma unroll
    for (int ii = 0; ii < 4; ii++) {
        int i = r0 + ii;
        float* row = P + (size_t)i * SEQ;
        float mx = -1e30f;
        for (int c = lane; c < SEQ; c += 32) mx = fmaxf(mx, row[c]);
#pragma unroll
        for (int o = 16; o; o >>= 1) mx = fmaxf(mx, __shfl_xor_sync(0xffffffffu, mx, o));
        float ssum = 0.f;
        for (int c = lane; c < SEQ; c += 32) {
            float e = __expf(row[c] - mx);
            row[c] = e;
            ssum += e;
        }
#pragma unroll
        for (int o = 16; o; o >>= 1) ssum += __shfl_xor_sync(0xffffffffu, ssum, o);
        float inv = 1.0f / ssum;
        float* grow = attn_base + (size_t)i * SEQ;
        for (int c = lane; c < SEQ; c += 32) {
            float p = row[c] * inv;
            row[c] = p;
            grow[c] = p;
        }
    }

    // ---- O = P @ V  (P reads are warp-broadcast: warp owns its rows) ----
    for (int kc = 0; kc < SEQ/CK; kc++) {
        __syncthreads();   // all warps past previous KV use
        const float* vbase = vh + (size_t)bh * SEQ * DK + (size_t)kc * CK * DK;
        for (int f = tid; f < CK*DK/4; f += 256)
            ((float4*)KV)[f] = ((const float4*)vbase)[f];   // Vs[kk][d], stride 64
        __syncthreads();

        const float* prow = P + (size_t)r0 * SEQ + kc*CK;
#pragma unroll 4
        for (int kk = 0; kk < CK; kk++) {
            float p0 = prow[kk];
            float p1 = prow[SEQ + kk];
            float p2 = prow[2*SEQ + kk];
            float p3 = prow[3*SEQ + kk];
            float v0 = KV[kk*DK + lane];
            float v1 = KV[kk*DK + lane + 32];
            accO[0][0] = fmaf(p0, v0, accO[0][0]); accO[0][1] = fmaf(p0, v1, accO[0][1]);
            accO[1][0] = fmaf(p1, v0, accO[1][0]); accO[1][1] = fmaf(p1, v1, accO[1][1]);
            accO[2][0] = fmaf(p2, v0, accO[2][0]); accO[2][1] = fmaf(p2, v1, accO[2][1]);
            accO[3][0] = fmaf(p3, v0, accO[3][0]); accO[3][1] = fmaf(p3, v1, accO[3][1]);
        }
    }

    // write O in concat layout [b][s][h*64+d]
#pragma unroll
    for (int ii = 0; ii < 4; ii++) {
        int s_ = qb*QB + r0 + ii;
        float* dstp = o_out + ((size_t)(b*SEQ + s_) * D_MODEL) + h*DK;
        dstp[lane]      = accO[ii][0];
        dstp[lane + 32] = accO[ii][1];
    }
}

// ---------------------------------------------------------------------------
// LayerNorm over rows of x[4096][1024]
// ---------------------------------------------------------------------------
__global__ __launch_bounds__(256) void ln_kernel(
    const float* __restrict__ x, const float* __restrict__ gamma,
    const float* __restrict__ beta, float* __restrict__ y)
{
    __shared__ float red[8];
    __shared__ float bval;
    const int r = blockIdx.x;
    const int tid = threadIdx.x, lane = tid & 31, warp = tid >> 5;
    const float* xr = x + (size_t)r * D_MODEL;

    float v[4];
    float s = 0.f;
#pragma unroll
    for (int u = 0; u < 4; u++) { v[u] = xr[tid + 256*u]; s += v[u]; }
#pragma unroll
    for (int o = 16; o; o >>= 1) s += __shfl_xor_sync(0xffffffffu, s, o);
    if (lane == 0) red[warp] = s;
    __syncthreads();
    if (tid == 0) {
        float t = 0.f;
#pragma unroll
        for (int w = 0; w < 8; w++) t += red[w];
        bval = t * (1.f / D_MODEL);
    }
    __syncthreads();
    float mean = bval;

    float sq = 0.f;
#pragma unroll
    for (int u = 0; u < 4; u++) { float d = v[u] - mean; sq += d * d; }
#pragma unroll
    for (int o = 16; o; o >>= 1) sq += __shfl_xor_sync(0xffffffffu, sq, o);
    __syncthreads();   // everyone has read mean & red before reuse
    if (lane == 0) red[warp] = sq;
    __syncthreads();
    if (tid == 0) {
        float t = 0.f;
#pragma unroll
        for (int w = 0; w < 8; w++) t += red[w];
        bval = rsqrtf(t * (1.f / D_MODEL) + 1e-5f);
    }
    __syncthreads();
    float rstd = bval;

#pragma unroll
    for (int u = 0; u < 4; u++) {
        int c = tid + 256*u;
        y[(size_t)r * D_MODEL + c] = (v[u] - mean) * rstd * gamma[c] + beta[c];
    }
}

// ---------------------------------------------------------------------------
extern "C" void kernel_launch(void* const* d_in, const int* in_sizes, int n_in,
                              void* d_out, int out_size)
{
    const float* q     = (const float*)d_in[0];
    const float* k     = (const float*)d_in[1];
    const float* v     = (const float*)d_in[2];
    const float* Wq    = (const float*)d_in[3];
    const float* bq    = (const float*)d_in[4];
    const float* Wk    = (const float*)d_in[5];
    const float* bk    = (const float*)d_in[6];
    const float* Wv    = (const float*)d_in[7];
    const float* bv    = (const float*)d_in[8];
    const float* Wfc   = (const float*)d_in[9];
    const float* bfc   = (const float*)d_in[10];
    const float* gamma = (const float*)d_in[11];
    const float* beta  = (const float*)d_in[12];

    float* out      = (float*)d_out;
    float* y_out    = out;                                   // [4,1024,1024]
    float* attn_out = out + (size_t)BATCH * SEQ * D_MODEL;   // [64,1024,1024]

    void* sp = nullptr;
    cudaGetSymbolAddress(&sp, g_scratch);
    float* qh = (float*)sp;
    float* kh = qh + NPH;
    float* vh = kh + NPH;
    float* oc = vh + NPH;
    float* xb = oc + NPH;

    const size_t attn_smem = (size_t)(QB*SEQ + QB*DK + CK*KPAD) * sizeof(float); // ~178KB
    cudaFuncSetAttribute(attn_kernel, cudaFuncAttributeMaxDynamicSharedMemorySize,
                         (int)attn_smem);

    dim3 gg(D_MODEL/128, M_TOK/128);   // (8, 32)
    sgemm_nt<0><<<gg, 256>>>(q, Wq, bq, nullptr, qh);
    sgemm_nt<0><<<gg, 256>>>(k, Wk, bk, nullptr, kh);
    sgemm_nt<0><<<gg, 256>>>(v, Wv, bv, nullptr, vh);

    attn_kernel<<<dim3(SEQ/QB, BATCH*NHEAD), 256, attn_smem>>>(qh, kh, vh, attn_out, oc);

    sgemm_nt<1><<<gg, 256>>>(oc, Wfc, bfc, q, xb);
    ln_kernel<<<M_TOK, 256>>>(xb, gamma, beta, y_out);
}

// round 11
// speedup vs baseline: 1.0018x; 1.0018x over previous
#include <cuda_runtime.h>
#include <cstdint>
#include <cstddef>

#define D_MODEL 1024
#define NHEAD   16
#define DK      64
#define BATCH   4
#define SEQ     1024
#define M_TOK   (BATCH*SEQ)    // 4096

#define QB   32     // q rows per attention block
#define CK   128    // k/v chunk columns
#define KPAD 76     // padded K-chunk row length (floats) -> conflict-free LDS.128

// scratch: qh, kh, vh, o_concat, x  (5 x 16MB)
#define NPH (BATCH*NHEAD*SEQ*DK)   // 4194304
__device__ float g_scratch[(size_t)5 * NPH];

// ---------------------------------------------------------------------------
// SGEMM (NT): C[M,N] = A[M,K] * W[N,K]^T + bias  (M=4096, N=K=1024)
// MODE 0: scatter to head layout dst[((b*16+h)*1024+s)*64+d]
// MODE 1: dst[m*1024+n] = C + bias + residual
// ---------------------------------------------------------------------------
template<int MODE>
__global__ __launch_bounds__(256) void sgemm_nt(
    const float* __restrict__ A, const float* __restrict__ W,
    const float* __restrict__ bias, const float* __restrict__ res,
    float* __restrict__ dst)
{
    const int K = D_MODEL;
    __shared__ float As[8][128];
    __shared__ float Bs[8][128];
    const int tid = threadIdx.x;
    const int m0 = blockIdx.y * 128;
    const int n0 = blockIdx.x * 128;
    const int lr = tid >> 1;           // 0..127
    const int lc = (tid & 1) << 2;     // 0 or 4
    const int ty = tid >> 4;           // 0..15
    const int tx = tid & 15;           // 0..15

    float acc[8][8];
#pragma unroll
    for (int i = 0; i < 8; i++)
#pragma unroll
        for (int j = 0; j < 8; j++) acc[i][j] = 0.f;

    const float* Ap = A + (size_t)(m0 + lr) * K + lc;
    const float* Wp = W + (size_t)(n0 + lr) * K + lc;

    for (int kt = 0; kt < K; kt += 8) {
        float4 a4 = *(const float4*)(Ap + kt);
        float4 b4 = *(const float4*)(Wp + kt);
        __syncthreads();
        As[lc+0][lr] = a4.x; As[lc+1][lr] = a4.y; As[lc+2][lr] = a4.z; As[lc+3][lr] = a4.w;
        Bs[lc+0][lr] = b4.x; Bs[lc+1][lr] = b4.y; Bs[lc+2][lr] = b4.z; Bs[lc+3][lr] = b4.w;
        __syncthreads();
#pragma unroll
        for (int kk = 0; kk < 8; kk++) {
            float4 a0 = *(const float4*)&As[kk][ty*4];
            float4 a1 = *(const float4*)&As[kk][64 + ty*4];
            float4 b0 = *(const float4*)&Bs[kk][tx*4];
            float4 b1 = *(const float4*)&Bs[kk][64 + tx*4];
            float ar[8] = {a0.x,a0.y,a0.z,a0.w,a1.x,a1.y,a1.z,a1.w};
            float br[8] = {b0.x,b0.y,b0.z,b0.w,b1.x,b1.y,b1.z,b1.w};
#pragma unroll
            for (int i = 0; i < 8; i++)
#pragma unroll
                for (int j = 0; j < 8; j++)
                    acc[i][j] = fmaf(ar[i], br[j], acc[i][j]);
        }
    }

#pragma unroll
    for (int i = 0; i < 8; i++) {
        int m = m0 + ((i < 4) ? (ty*4 + i) : (64 + ty*4 + i - 4));
#pragma unroll
        for (int j = 0; j < 8; j++) {
            int n = n0 + ((j < 4) ? (tx*4 + j) : (64 + tx*4 + j - 4));
            float v = acc[i][j] + bias[n];
            if (MODE == 0) {
                int bb = m >> 10, ss = m & 1023, hh = n >> 6, dd = n & 63;
                dst[(((size_t)(bb*NHEAD + hh) * SEQ + ss) << 6) + dd] = v;
            } else {
                size_t idx = (size_t)m * D_MODEL + n;
                dst[idx] = v + res[idx];
            }
        }
    }
}

// ---------------------------------------------------------------------------
// Fused attention: per (b,h, 32-row q block):
//   scores(32x1024) in smem -> softmax -> write attn to gmem -> O = P @ V
// No 1/sqrt(dk) scaling (faithful to reference).
// ---------------------------------------------------------------------------
__global__ __launch_bounds__(256) void attn_kernel(
    const float* __restrict__ qh, const float* __restrict__ kh,
    const float* __restrict__ vh,
    float* __restrict__ attn_out, float* __restrict__ o_out)
{
    extern __shared__ float sm[];
    float* P  = sm;                  // [32][1024]
    float* Qs = P + QB*SEQ;          // [32][64]
    float* KV = Qs + QB*DK;          // [128][76] for K (padded) / [128][64] for V

    const int tid  = threadIdx.x;
    const int bh   = blockIdx.y;         // b*16 + h
    const int qb   = blockIdx.x;         // 0..31
    const int b    = bh >> 4, h = bh & 15;
    const int warp = tid >> 5, lane = tid & 31;
    const int r0   = warp * 4;           // this warp's 4 rows

    // load Q tile (contiguous copy)
    const float* qbase = qh + (size_t)bh * SEQ * DK + (size_t)qb * QB * DK;
#pragma unroll
    for (int f = tid; f < QB*DK/4; f += 256)
        ((float4*)Qs)[f] = ((const float4*)qbase)[f];

    float accO[4][2] = {{0.f,0.f},{0.f,0.f},{0.f,0.f},{0.f,0.f}};

    // ---- scores: S[i][j] = Q[i] . K[j] ----
    for (int kc = 0; kc < SEQ/CK; kc++) {
        __syncthreads();
        const float* kbase = kh + (size_t)bh * SEQ * DK + (size_t)kc * CK * DK;
        for (int f = tid; f < CK*DK/4; f += 256) {
            int j = f >> 4, k4 = f & 15;
            float4 kv4 = ((const float4*)kbase)[f];
            *(float4*)&KV[j*KPAD + k4*4] = kv4;
        }
        __syncthreads();

        float acc[4][4];
#pragma unroll
        for (int ii = 0; ii < 4; ii++)
#pragma unroll
            for (int jj = 0; jj < 4; jj++) acc[ii][jj] = 0.f;

#pragma unroll 4
        for (int k4 = 0; k4 < DK/4; k4++) {
            float4 q0 = *(const float4*)&Qs[(r0+0)*DK + k4*4];
            float4 q1 = *(const float4*)&Qs[(r0+1)*DK + k4*4];
            float4 q2 = *(const float4*)&Qs[(r0+2)*DK + k4*4];
            float4 q3 = *(const float4*)&Qs[(r0+3)*DK + k4*4];
#pragma unroll
            for (int jj = 0; jj < 4; jj++) {
                float4 kv4 = *(const float4*)&KV[(lane + 32*jj)*KPAD + k4*4];
                acc[0][jj] += q0.x*kv4.x + q0.y*kv4.y + q0.z*kv4.z + q0.w*kv4.w;
                acc[1][jj] += q1.x*kv4.x + q1.y*kv4.y + q1.z*kv4.z + q1.w*kv4.w;
                acc[2][jj] += q2.x*kv4.x + q2.y*kv4.y + q2.z*kv4.z + q2.w*kv4.w;
                acc[3][jj] += q3.x*kv4.x + q3.y*kv4.y + q3.z*kv4.z + q3.w*kv4.w;
            }
        }
#pragma unroll
        for (int ii = 0; ii < 4; ii++)
#pragma unroll
            for (int jj = 0; jj < 4; jj++)
                P[(r0+ii)*SEQ + kc*CK + lane + 32*jj] = acc[ii][jj];
    }

    // ---- softmax on this warp's own 4 rows + write attn to gmem ----
    float* attn_base = attn_out + ((size_t)(h*BATCH + b) * SEQ + (size_t)qb*QB) * SEQ;
#pragma unroll
    for (int ii = 0; ii < 4; ii++) {
        int i = r0 + ii;
        float* row = P + (size_t)i * SEQ;
        float mx = -1e30f;
        for (int c = lane; c < SEQ; c += 32) mx = fmaxf(mx, row[c]);
#pragma unroll
        for (int o = 16; o; o >>= 1) mx = fmaxf(mx, __shfl_xor_sync(0xffffffffu, mx, o));
        float ssum = 0.f;
        for (int c = lane; c < SEQ; c += 32) {
            float e = __expf(row[c] - mx);
            row[c] = e;
            ssum += e;
        }
#pragma unroll
        for (int o = 16; o; o >>= 1) ssum += __shfl_xor_sync(0xffffffffu, ssum, o);
        float inv = 1.0f / ssum;
        float* grow = attn_base + (size_t)i * SEQ;
        for (int c = lane; c < SEQ; c += 32) {
            float p = row[c] * inv;
            row[c] = p;
            grow[c] = p;
        }
    }

    // ---- O = P @ V  (P reads are warp-broadcast: warp owns its rows) ----
    for (int kc = 0; kc < SEQ/CK; kc++) {
        __syncthreads();   // all warps past previous KV use
        const float* vbase = vh + (size_t)bh * SEQ * DK + (size_t)kc * CK * DK;
        for (int f = tid; f < CK*DK/4; f += 256)
            ((float4*)KV)[f] = ((const float4*)vbase)[f];   // Vs[kk][d], stride 64
        __syncthreads();

        const float* prow = P + (size_t)r0 * SEQ + kc*CK;
#pragma unroll 4
        for (int kk = 0; kk < CK; kk++) {
            float p0 = prow[kk];
            float p1 = prow[SEQ + kk];
            float p2 = prow[2*SEQ + kk];
            float p3 = prow[3*SEQ + kk];
            float v0 = KV[kk*DK + lane];
            float v1 = KV[kk*DK + lane + 32];
            accO[0][0] = fmaf(p0, v0, accO[0][0]); accO[0][1] = fmaf(p0, v1, accO[0][1]);
            accO[1][0] = fmaf(p1, v0, accO[1][0]); accO[1][1] = fmaf(p1, v1, accO[1][1]);
            accO[2][0] = fmaf(p2, v0, accO[2][0]); accO[2][1] = fmaf(p2, v1, accO[2][1]);
            accO[3][0] = fmaf(p3, v0, accO[3][0]); accO[3][1] = fmaf(p3, v1, accO[3][1]);
        }
    }

    // write O in concat layout [b][s][h*64+d]
#pragma unroll
    for (int ii = 0; ii < 4; ii++) {
        int s_ = qb*QB + r0 + ii;
        float* dstp = o_out + ((size_t)(b*SEQ + s_) * D_MODEL) + h*DK;
        dstp[lane]      = accO[ii][0];
        dstp[lane + 32] = accO[ii][1];
    }
}

// ---------------------------------------------------------------------------
// LayerNorm over rows of x[4096][1024]
// ---------------------------------------------------------------------------
__global__ __launch_bounds__(256) void ln_kernel(
    const float* __restrict__ x, const float* __restrict__ gamma,
    const float* __restrict__ beta, float* __restrict__ y)
{
    __shared__ float red[8];
    __shared__ float bval;
    const int r = blockIdx.x;
    const int tid = threadIdx.x, lane = tid & 31, warp = tid >> 5;
    const float* xr = x + (size_t)r * D_MODEL;

    float v[4];
    float s = 0.f;
#pragma unroll
    for (int u = 0; u < 4; u++) { v[u] = xr[tid + 256*u]; s += v[u]; }
#pragma unroll
    for (int o = 16; o; o >>= 1) s += __shfl_xor_sync(0xffffffffu, s, o);
    if (lane == 0) red[warp] = s;
    __syncthreads();
    if (tid == 0) {
        float t = 0.f;
#pragma unroll
        for (int w = 0; w < 8; w++) t += red[w];
        bval = t * (1.f / D_MODEL);
    }
    __syncthreads();
    float mean = bval;

    float sq = 0.f;
#pragma unroll
    for (int u = 0; u < 4; u++) { float d = v[u] - mean; sq += d * d; }
#pragma unroll
    for (int o = 16; o; o >>= 1) sq += __shfl_xor_sync(0xffffffffu, sq, o);
    __syncthreads();   // everyone has read mean & red before reuse
    if (lane == 0) red[warp] = sq;
    __syncthreads();
    if (tid == 0) {
        float t = 0.f;
#pragma unroll
        for (int w = 0; w < 8; w++) t += red[w];
        bval = rsqrtf(t * (1.f / D_MODEL) + 1e-5f);
    }
    __syncthreads();
    float rstd = bval;

#pragma unroll
    for (int u = 0; u < 4; u++) {
        int c = tid + 256*u;
        y[(size_t)r * D_MODEL + c] = (v[u] - mean) * rstd * gamma[c] + beta[c];
    }
}

// ---------------------------------------------------------------------------
extern "C" void kernel_launch(void* const* d_in, const int* in_sizes, int n_in,
                              void* d_out, int out_size)
{
    const float* q     = (const float*)d_in[0];
    const float* k     = (const float*)d_in[1];
    const float* v     = (const float*)d_in[2];
    const float* Wq    = (const float*)d_in[3];
    const float* bq    = (const float*)d_in[4];
    const float* Wk    = (const float*)d_in[5];
    const float* bk    = (const float*)d_in[6];
    const float* Wv    = (const float*)d_in[7];
    const float* bv    = (const float*)d_in[8];
    const float* Wfc   = (const float*)d_in[9];
    const float* bfc   = (const float*)d_in[10];
    const float* gamma = (const float*)d_in[11];
    const float* beta  = (const float*)d_in[12];

    float* out      = (float*)d_out;
    float* y_out    = out;                                   // [4,1024,1024]
    float* attn_out = out + (size_t)BATCH * SEQ * D_MODEL;   // [64,1024,1024]

    void* sp = nullptr;
    cudaGetSymbolAddress(&sp, g_scratch);
    float* qh = (float*)sp;
    float* kh = qh + NPH;
    float* vh = kh + NPH;
    float* oc = vh + NPH;
    float* xb = oc + NPH;

    const size_t attn_smem = (size_t)(QB*SEQ + QB*DK + CK*KPAD) * sizeof(float); // ~178KB
    cudaFuncSetAttribute(attn_kernel, cudaFuncAttributeMaxDynamicSharedMemorySize,
                         (int)attn_smem);

    dim3 gg(D_MODEL/128, M_TOK/128);   // (8, 32)
    sgemm_nt<0><<<gg, 256>>>(q, Wq, bq, nullptr, qh);
    sgemm_nt<0><<<gg, 256>>>(k, Wk, bk, nullptr, kh);
    sgemm_nt<0><<<gg, 256>>>(v, Wv, bv, nullptr, vh);

    attn_kernel<<<dim3(SEQ/QB, BATCH*NHEAD), 256, attn_smem>>>(qh, kh, vh, attn_out, oc);

    sgemm_nt<1><<<gg, 256>>>(oc, Wfc, bfc, q, xb);
    ln_kernel<<<M_TOK, 256>>>(xb, gamma, beta, y_out);
}